// round 7
// baseline (speedup 1.0000x reference)
#include <cuda_runtime.h>
#include <cuda_bf16.h>
#include <cstdint>

// GDLoss: elementwise Gaussian KL loss over [N,5] xywhr boxes. 176MB traffic.
// R7: R6 persistent 3-stage cp.async pipeline, but issue-side slimmed:
//  - rcp.approx / sqrt.approx instead of correctly-rounded rcp/sqrt (~25 ops/box)
//  - double-angle identities for the covariance terms (~10 ops/box)
//  - pure int32 addressing (no 64-bit IMAD chains)
// R6 profile showed issue=82% / DRAM=71%: scheduler-bound, not memory-bound.

#define TAU_F   1.0f
#define EPS_F   1e-6f
#define BLK     256
#define STAGES  3
#define TILE_F  (BLK * 5)            // 1280 floats per tensor per tile
#define TILE_V4 (TILE_F / 4)         // 320 float4 per tensor per tile
#define GRID_P  1064                 // 7 blocks/SM * 152 SMs

__device__ __forceinline__ void cp_async16(unsigned smem_dst, const void* gmem_src) {
    asm volatile("cp.async.cg.shared.global [%0], [%1], 16;\n"
                 :: "r"(smem_dst), "l"(gmem_src));
}
__device__ __forceinline__ void cp_async4(unsigned smem_dst, const void* gmem_src) {
    asm volatile("cp.async.ca.shared.global [%0], [%1], 4;\n"
                 :: "r"(smem_dst), "l"(gmem_src));
}
__device__ __forceinline__ void cp_commit() {
    asm volatile("cp.async.commit_group;\n" ::: "memory");
}
template <int N>
__device__ __forceinline__ void cp_wait() {
    asm volatile("cp.async.wait_group %0;\n" :: "n"(N) : "memory");
}

__device__ __forceinline__ float rcp_fast(float x) {
    float r; asm("rcp.approx.f32 %0, %1;" : "=f"(r) : "f"(x)); return r;
}
__device__ __forceinline__ float sqrt_fast(float x) {
    float r; asm("sqrt.approx.f32 %0, %1;" : "=f"(r) : "f"(x)); return r;
}

__device__ __forceinline__ float gd_loss_one(
    float px, float py, float pw, float ph, float prr,
    float tx, float ty, float tw, float th, float trr)
{
    pw = fminf(fmaxf(pw, 1e-7f), 1e7f);
    ph = fminf(fmaxf(ph, 1e-7f), 1e7f);
    tw = fminf(fmaxf(tw, 1e-7f), 1e7f);
    th = fminf(fmaxf(th, 1e-7f), 1e7f);

    // sigma = R diag((w/2)^2,(h/2)^2) R^T via double-angle:
    //   s11 = hs + hd*cos2r, s12 = hd*sin2r, s22 = hs - hd*cos2r
    //   hs = (ww+hh)/8, hd = (ww-hh)/8   (the /8 = /4 halved)
    const float pww = pw * pw, phh = ph * ph;
    const float phs = 0.125f * (pww + phh);
    const float phd = 0.125f * (pww - phh);
    float ps2, pc2;
    __sincosf(2.0f * prr, &ps2, &pc2);
    const float p11 = fmaf(phd, pc2, phs);
    const float p12 = phd * ps2;
    const float p22 = fmaf(-phd, pc2, phs);

    const float tww = tw * tw, thh = th * th;
    const float ths = 0.125f * (tww + thh);
    const float thd = 0.125f * (tww - thh);
    float ts2, tc2;
    __sincosf(2.0f * trr, &ts2, &tc2);
    const float t11 = fmaf(thd, tc2, ths);
    const float t12 = thd * ts2;
    const float t22 = fmaf(-thd, tc2, ths);

    const float det_p = fmaf(p11, p22, -p12 * p12);
    const float det_t = fmaf(t11, t22, -t12 * t12);

    const float dx = px - tx;
    const float dy = py - ty;

    const float inv_det_t = rcp_fast(det_t);

    const float num1 = fmaf(t22 * dx, dx, fmaf(-2.0f * t12, dx * dy, t11 * dy * dy));
    const float num2 = fmaf(t22, p11, fmaf(-2.0f * t12, p12, t11 * p22));
    const float dis = fmaf(num1 + num2, inv_det_t,
                           __logf(det_t * rcp_fast(det_p)) - 2.0f);

    const float kl = fmaxf(dis, EPS_F);
    return 1.0f - rcp_fast(TAU_F + sqrt_fast(kl));
}

__global__ void __launch_bounds__(BLK) gd_loss_kernel(
    const float* __restrict__ pred,
    const float* __restrict__ target,
    float* __restrict__ out,
    int n)
{
    __shared__ float sp[STAGES][TILE_F];
    __shared__ float st[STAGES][TILE_F];

    const int tid = threadIdx.x;
    const int numTiles = (n + BLK - 1) / BLK;      // <= 15625: int32-safe
    const int stride = gridDim.x;

    // Issue cp.async loads for tile t into ring slot. Always commits.
    auto issue = [&](int t, int slot) {
        if (t < numTiles) {
            const int tileBase = t * BLK;          // <= 4M
            const int nb = n - tileBase;
            float* spb = sp[slot];
            float* stb = st[slot];
            const float* pbase = pred   + tileBase * 5;   // <= 20M: int32-safe
            const float* tbase = target + tileBase * 5;
            if (nb >= BLK) {
                const float4* p4 = (const float4*)pbase;
                const float4* t4 = (const float4*)tbase;
                #pragma unroll
                for (int j = 0; j < 2; ++j) {
                    const int i = tid + j * BLK;
                    if (i < TILE_V4) {
                        cp_async16((unsigned)__cvta_generic_to_shared(((float4*)spb) + i), p4 + i);
                        cp_async16((unsigned)__cvta_generic_to_shared(((float4*)stb) + i), t4 + i);
                    }
                }
            } else {
                const int nfloats = nb * 5;
                for (int i = tid; i < nfloats; i += BLK) {
                    cp_async4((unsigned)__cvta_generic_to_shared(spb + i), pbase + i);
                    cp_async4((unsigned)__cvta_generic_to_shared(stb + i), tbase + i);
                }
            }
        }
        cp_commit();
    };

    // Prologue: two tiles in flight.
    issue(blockIdx.x, 0);
    issue(blockIdx.x + stride, 1);

    int slot = 0;
    for (int tile = blockIdx.x; tile < numTiles; tile += stride) {
        cp_wait<1>();        // tile's data landed (next still in flight)
        __syncthreads();     // prev compute done -> oldest buffer free
        // issue tile+2*stride into the slot being freed (slot-1 mod 3 == slot+2 mod 3)
        int islot = slot + 2; if (islot >= STAGES) islot -= STAGES;
        issue(tile + 2 * stride, islot);

        const int tileBase = tile * BLK;
        const int nb = n - tileBase;

        if (tid < nb) {      // nb >= BLK for full tiles -> always true
            const float* spb = sp[slot];
            const float* stb = st[slot];
            const int b5 = tid * 5;   // stride-5 smem: gcd(5,32)=1, conflict-free
            const float loss = gd_loss_one(
                spb[b5 + 0], spb[b5 + 1], spb[b5 + 2], spb[b5 + 3], spb[b5 + 4],
                stb[b5 + 0], stb[b5 + 1], stb[b5 + 2], stb[b5 + 3], stb[b5 + 4]);
            out[tileBase + tid] = loss;
        }

        ++slot; if (slot >= STAGES) slot = 0;
    }
}

extern "C" void kernel_launch(void* const* d_in, const int* in_sizes, int n_in,
                              void* d_out, int out_size)
{
    const float* pred   = (const float*)d_in[0];
    const float* target = (const float*)d_in[1];
    // d_in[2] (weight) is unused by the reference computation (LOSS_WEIGHT=1).
    float* out = (float*)d_out;

    const int n = out_size;                      // N boxes; output is [N,1] floats
    const int numTiles = (n + BLK - 1) / BLK;    // 15625 for N=4M
    int grid = GRID_P;
    if (grid > numTiles) grid = numTiles;
    gd_loss_kernel<<<grid, BLK>>>(pred, target, out, n);
}

// round 8
// speedup vs baseline: 1.0077x; 1.0077x over previous
#include <cuda_runtime.h>
#include <cuda_bf16.h>
#include <cstdint>

// GDLoss: elementwise Gaussian KL loss over [N,5] xywhr boxes. 176MB traffic.
// R8: algebraic rewrite + 2 boxes/thread.
//  - det(sigma) = w^2 h^2 / 16 exactly (no trig): dets need zero trig.
//  - trace/xy terms via double-angle: pred covariance collapses into ONE
//    __cosf(2(rt-rp)); only target needs a sincos. 3 MUFU trig total.
//  - 2 boxes/thread: LDS.64 (stride-10-word = conflict-free), STG.64 out.
//  - persistent 2-stage cp.async ring, 512-box tiles, 40KB smem, 5 blocks/SM.
// R5-R7 plateaued at ~30us with issue 70-82% / DRAM 67-72% (co-limited);
// this cuts issued instructions ~40% to let DRAM rise.

#define TAU_F   1.0f
#define EPS_F   1e-6f
#define BLK     256
#define BPT     512                   // boxes per tile (2 per thread)
#define TILE_F  (BPT * 5)             // 2560 floats per tensor per tile
#define TILE_V4 (TILE_F / 4)          // 640 float4 per tensor per tile
#define STAGES  2
#define GRID_P  760                   // 5 blocks/SM * 152 SMs

__device__ __forceinline__ void cp_async16(unsigned smem_dst, const void* gmem_src) {
    asm volatile("cp.async.cg.shared.global [%0], [%1], 16;\n"
                 :: "r"(smem_dst), "l"(gmem_src));
}
__device__ __forceinline__ void cp_async4(unsigned smem_dst, const void* gmem_src) {
    asm volatile("cp.async.ca.shared.global [%0], [%1], 4;\n"
                 :: "r"(smem_dst), "l"(gmem_src));
}
__device__ __forceinline__ void cp_commit() {
    asm volatile("cp.async.commit_group;\n" ::: "memory");
}
template <int N>
__device__ __forceinline__ void cp_wait() {
    asm volatile("cp.async.wait_group %0;\n" :: "n"(N) : "memory");
}

__device__ __forceinline__ float rcp_fast(float x) {
    float r; asm("rcp.approx.f32 %0, %1;" : "=f"(r) : "f"(x)); return r;
}
__device__ __forceinline__ float sqrt_fast(float x) {
    float r; asm("sqrt.approx.f32 %0, %1;" : "=f"(r) : "f"(x)); return r;
}

// loss for one box pair, using:
//   det_t = tww*thh/16, det_p = pww*phh/16  (exact, no trig)
//   t1num = ths(dx^2+dy^2) - thd(c2t(dx^2-dy^2) + 2 s2t dx dy)
//   n2num = 2(ths*phs - thd*phd*cos(2rt-2rp))
//   dis   = (t1num+n2num)*16/(tww*thh) + log((tww*thh)/(pww*phh)) - 2
__device__ __forceinline__ float gd_loss_one(
    float px, float py, float pw, float ph, float prr,
    float tx, float ty, float tw, float th, float trr)
{
    pw = fminf(fmaxf(pw, 1e-7f), 1e7f);
    ph = fminf(fmaxf(ph, 1e-7f), 1e7f);
    tw = fminf(fmaxf(tw, 1e-7f), 1e7f);
    th = fminf(fmaxf(th, 1e-7f), 1e7f);

    const float pww = pw * pw, phh = ph * ph;
    const float tww = tw * tw, thh = th * th;

    const float phs = 0.125f * (pww + phh);
    const float phd = 0.125f * (pww - phh);
    const float ths = 0.125f * (tww + thh);
    const float thd = 0.125f * (tww - thh);

    float s2t, c2t;
    __sincosf(2.0f * trr, &s2t, &c2t);
    const float cdd = __cosf(2.0f * (trr - prr));   // cos(2rt-2rp)

    const float dx = px - tx;
    const float dy = py - ty;
    const float dx2 = dx * dx, dy2 = dy * dy;
    const float sum2 = dx2 + dy2, dif2 = dx2 - dy2;
    const float dxy = dx * dy;

    // t1num = ths*sum2 - thd*(c2t*dif2 + 2*s2t*dxy)
    const float rot = fmaf(c2t, dif2, 2.0f * s2t * dxy);
    const float t1num = fmaf(ths, sum2, -thd * rot);
    // n2num = 2*(ths*phs - thd*phd*cdd)
    const float n2num = 2.0f * fmaf(-thd * phd, cdd, ths * phs);

    const float dtt = tww * thh;                    // 16*det_t
    const float dpp = pww * phh;                    // 16*det_p
    const float invdt16 = 16.0f * rcp_fast(dtt);
    const float logterm = __logf(dtt * rcp_fast(dpp));

    const float dis = fmaf(t1num + n2num, invdt16, logterm - 2.0f);
    const float kl = fmaxf(dis, EPS_F);
    return 1.0f - rcp_fast(TAU_F + sqrt_fast(kl));
}

__global__ void __launch_bounds__(BLK) gd_loss_kernel(
    const float* __restrict__ pred,
    const float* __restrict__ target,
    float* __restrict__ out,
    int n)
{
    __shared__ float sp[STAGES][TILE_F];
    __shared__ float st[STAGES][TILE_F];

    const int tid = threadIdx.x;
    const int numTiles = (n + BPT - 1) / BPT;
    const int stride = gridDim.x;

    // Issue cp.async for tile t into ring slot. Always commits one group.
    auto issue = [&](int t, int slot) {
        if (t < numTiles) {
            const int tileBase = t * BPT;
            const int nb = n - tileBase;            // boxes remaining
            float* spb = sp[slot];
            float* stb = st[slot];
            const float* pbase = pred   + tileBase * 5;   // <=20M: int32-safe
            const float* tbase = target + tileBase * 5;
            if (nb >= BPT) {
                const float4* p4 = (const float4*)pbase;
                const float4* t4 = (const float4*)tbase;
                #pragma unroll
                for (int j = 0; j < 3; ++j) {
                    const int i = tid + j * BLK;
                    if (i < TILE_V4) {
                        cp_async16((unsigned)__cvta_generic_to_shared(((float4*)spb) + i), p4 + i);
                        cp_async16((unsigned)__cvta_generic_to_shared(((float4*)stb) + i), t4 + i);
                    }
                }
            } else {
                const int nfloats = nb * 5;
                for (int i = tid; i < nfloats; i += BLK) {
                    cp_async4((unsigned)__cvta_generic_to_shared(spb + i), pbase + i);
                    cp_async4((unsigned)__cvta_generic_to_shared(stb + i), tbase + i);
                }
            }
        }
        cp_commit();
    };

    // Prologue: two tiles in flight.
    issue(blockIdx.x, 0);
    issue(blockIdx.x + stride, 1);

    int slot = 0;
    for (int tile = blockIdx.x; tile < numTiles; tile += stride) {
        cp_wait<1>();        // this tile's group done (next still in flight)
        __syncthreads();     // all threads' copies for this tile visible

        const int tileBase = tile * BPT;
        const int nb = n - tileBase;                 // >= BPT for full tiles
        const float* spb = sp[slot];
        const float* stb = st[slot];

        const int b = 2 * tid;                        // first box of this thread
        // 5 x LDS.64, stride 10 words: conflict-free (gcd trick), 8B aligned.
        const float2* p2 = (const float2*)(spb + 10 * tid);
        const float2* t2 = (const float2*)(stb + 10 * tid);

        if (b + 1 < nb) {                             // both boxes valid (common)
            const float2 pA = p2[0], pB = p2[1], pC = p2[2], pD = p2[3], pE = p2[4];
            const float2 tA = t2[0], tB = t2[1], tC = t2[2], tD = t2[3], tE = t2[4];
            float2 res;
            res.x = gd_loss_one(pA.x, pA.y, pB.x, pB.y, pC.x,
                                tA.x, tA.y, tB.x, tB.y, tC.x);
            res.y = gd_loss_one(pC.y, pD.x, pD.y, pE.x, pE.y,
                                tC.y, tD.x, tD.y, tE.x, tE.y);
            *(float2*)(out + tileBase + b) = res;
        } else if (b < nb) {                          // tail: single box
            const float2 pA = p2[0], pB = p2[1];
            const float  pE = spb[10 * tid + 4];
            const float2 tA = t2[0], tB = t2[1];
            const float  tE = stb[10 * tid + 4];
            out[tileBase + b] = gd_loss_one(pA.x, pA.y, pB.x, pB.y, pE,
                                            tA.x, tA.y, tB.x, tB.y, tE);
        }

        __syncthreads();     // everyone done reading this slot
        issue(tile + 2 * stride, slot);   // refill same slot
        slot ^= 1;
    }
}

extern "C" void kernel_launch(void* const* d_in, const int* in_sizes, int n_in,
                              void* d_out, int out_size)
{
    const float* pred   = (const float*)d_in[0];
    const float* target = (const float*)d_in[1];
    // d_in[2] (weight) is unused by the reference computation (LOSS_WEIGHT=1).
    float* out = (float*)d_out;

    const int n = out_size;                      // N boxes; output is [N,1] floats
    const int numTiles = (n + BPT - 1) / BPT;    // 7813 for N=4M
    int grid = GRID_P;
    if (grid > numTiles) grid = numTiles;
    gd_loss_kernel<<<grid, BLK>>>(pred, target, out, n);
}